// round 4
// baseline (speedup 1.0000x reference)
#include <cuda_runtime.h>
#include <cuda_bf16.h>

// ---------------------------------------------------------------------------
// NetMHCpan BiLSTM (pep 15 steps + hla 372 steps, H=1024) + MLP(4096->4096->1)
//
//  K0 init : zero per-replay flags, set step-0 flags, zero h(t=0)
//  K1 xg   : xg[l][t][4096] = x_t @ wih^T + bih + bhh   (handles seq reversal)
//  K2 lstm : persistent 148-CTA kernel; 74 CTAs per direction; each CTA owns
//            13-14 hidden indices -> 52-56 rows of Whh resident in SMEM (fp32).
//            Per step: warp0 polls 74 per-producer release flags (distinct
//            addresses -> no atomic serialization), warps load h[t-1] from
//            L2/L1, SMEM-streamed dot products, local gating (c per-CTA),
//            write own h slice, threadfence + per-CTA release flag.
//  K3 mlp1 : h1 = relu(x_cat @ w1^T + b1)
//  K4 mlp2 : out = h1 @ w2^T + b2
//
//  SMEM budget (k_lstm): dynamic 229376 B (weights) + static 280 B < 232448 B.
// ---------------------------------------------------------------------------

#define TMAX   372
#define LP     15
#define H      1024
#define NGATE  4096
#define NCTA_L 74          // CTAs per LSTM direction
#define GRID   148
#define NTHR   256

#define MAXIDX 14          // max hidden indices per CTA
#define MAXROW (MAXIDX*4)  // 56
#define SMEM_BYTES (MAXROW*1024*4)   // 229376 B: weight rows only

struct Ptrs {
    const float* x_pep;
    const float* x_hla;
    const float* wih[4];
    const float* whh[4];
    const float* bih[4];
    const float* bhh[4];
    const float* w1;
    const float* b1;
    const float* w2;
    const float* b2;
};

// l: 0=pep_f 1=pep_b 2=hla_f 3=hla_b
__device__ float    g_h[4][TMAX + 1][H];         // hidden states per step
__device__ float    g_xg[4][TMAX][NGATE];        // input projections + biases
__device__ unsigned g_flag[4][TMAX + 1][NCTA_L]; // per-producer ready flags
__device__ float    g_h1[NGATE];                 // MLP hidden

#define NFLAG (4 * (TMAX + 1) * NCTA_L)

__device__ __forceinline__ float sigf(float x) {
    return 1.0f / (1.0f + __expf(-x));
}
__device__ __forceinline__ float tanhf_(float x) {
    float e = __expf(2.0f * x);
    return 1.0f - 2.0f / (e + 1.0f);
}

// ---------------------------------------------------------------- K0: init
__global__ void k_init() {
    int tid = blockIdx.x * blockDim.x + threadIdx.x;
    if (tid < NFLAG) {
        // flag[l][0][*] = 1 (step 0 ready), all others 0
        int rem = tid % ((TMAX + 1) * NCTA_L);
        ((unsigned*)g_flag)[tid] = (rem < NCTA_L) ? 1u : 0u;
    }
    if (tid < 4 * H) {
        int l = tid >> 10;
        g_h[l][0][tid & (H - 1)] = 0.0f;
    }
}

// ---------------------------------------------------------------- K1: xg
__global__ void k_xg(Ptrs P) {
    int t = blockIdx.x;
    int l = blockIdx.y;
    int T = (l < 2) ? LP : TMAX;
    if (t >= T) return;
    const float* x = (l < 2) ? P.x_pep : P.x_hla;
    int te = (l & 1) ? (T - 1 - t) : t;      // backward dir: reversed input

    __shared__ float xs[21];
    if (threadIdx.x < 21) xs[threadIdx.x] = x[te * 21 + threadIdx.x];
    __syncthreads();

    const float* wih = P.wih[l];
    const float* ba  = P.bih[l];
    const float* bb  = P.bhh[l];
    for (int r = threadIdx.x; r < NGATE; r += blockDim.x) {
        float a = ba[r] + bb[r];
        const float* w = wih + r * 21;
#pragma unroll
        for (int i = 0; i < 21; i++) a = fmaf(xs[i], w[i], a);
        g_xg[l][t][r] = a;
    }
}

// ---------------------------------------------------------------- K2: lstm
__global__ void __launch_bounds__(NTHR, 1) k_lstm(Ptrs P) {
    extern __shared__ float w_s[];           // [nrows][1024]
    __shared__ float rowsum[MAXROW];
    __shared__ float c_s[MAXIDX];

    const int tid  = threadIdx.x;
    const int lane = tid & 31;
    const int warp = tid >> 5;
    const int cta  = blockIdx.x;
    const int dir  = (cta >= NCTA_L) ? 1 : 0;
    const int cid  = cta - dir * NCTA_L;
    const int jb   = (cid * H) / NCTA_L;
    const int je   = ((cid + 1) * H) / NCTA_L;
    const int nidx = je - jb;                // 13 or 14
    const int nrows = nidx * 4;

    for (int phase = 0; phase < 2; phase++) {
        const int l = phase * 2 + dir;
        const int T = phase ? TMAX : LP;
        const float4* whh4 = (const float4*)P.whh[l];

        __syncthreads();   // protect w_s / c_s reuse across phases
        // load this CTA's weight rows: local row r = li*4 + gate
        for (int idx = tid; idx < nrows * 256; idx += NTHR) {
            int r  = idx >> 8;
            int c4 = idx & 255;
            int li = r >> 2, g = r & 3;
            int grow = g * H + jb + li;      // global row in [4096,1024]
            ((float4*)w_s)[idx] = whh4[grow * 256 + c4];
        }
        if (tid < MAXIDX) c_s[tid] = 0.0f;
        __syncthreads();

        for (int t = 1; t <= T; t++) {
            // ---- prefetch xg gate values (independent of h[t-1])
            float pxi = 0.f, pxf = 0.f, pxg = 0.f, pxo = 0.f;
            if (tid < nidx) {
                const float* xg = g_xg[l][t - 1];
                int j = jb + tid;
                pxi = xg[j];
                pxf = xg[H + j];
                pxg = xg[2 * H + j];
                pxo = xg[3 * H + j];
            }

            // ---- wait for all 74 producers of h[t-1] (per-CTA flags)
            if (warp == 0) {
                const unsigned* fl = g_flag[l][t - 1];
                bool done;
                do {
                    unsigned ok = 1u;
#pragma unroll
                    for (int k = 0; k < 3; k++) {
                        int f = lane + k * 32;
                        if (f < NCTA_L) {
                            unsigned v;
                            asm volatile("ld.acquire.gpu.u32 %0, [%1];"
                                         : "=r"(v) : "l"(&fl[f]) : "memory");
                            ok &= v;
                        }
                    }
                    done = __all_sync(0xffffffffu, ok != 0u);
                } while (!done);
            }
            __syncthreads();

            // ---- load full h[t-1] (warp0 misses to L2, others hit L1)
            const float4* hsrc = (const float4*)g_h[l][t - 1];
            float4 h4[8];
#pragma unroll
            for (int k = 0; k < 8; k++) h4[k] = hsrc[k * 32 + lane];

            // ---- dot products: warp per row, lanes cover cols k*128+lane*4
            for (int r = warp; r < nrows; r += (NTHR / 32)) {
                const float4* wr = (const float4*)(w_s + (r << 10));
                float a0 = 0.f, a1 = 0.f, a2 = 0.f, a3 = 0.f;
#pragma unroll
                for (int k = 0; k < 8; k++) {
                    float4 w = wr[k * 32 + lane];
                    a0 = fmaf(w.x, h4[k].x, a0);
                    a1 = fmaf(w.y, h4[k].y, a1);
                    a2 = fmaf(w.z, h4[k].z, a2);
                    a3 = fmaf(w.w, h4[k].w, a3);
                }
                float a = (a0 + a1) + (a2 + a3);
#pragma unroll
                for (int off = 16; off; off >>= 1)
                    a += __shfl_xor_sync(0xffffffffu, a, off);
                if (lane == 0) rowsum[r] = a;
            }
            __syncthreads();

            // ---- gating for owned hidden indices (c is CTA-local)
            if (tid < nidx) {
                float vi = rowsum[tid * 4 + 0] + pxi;
                float vf = rowsum[tid * 4 + 1] + pxf;
                float vg = rowsum[tid * 4 + 2] + pxg;
                float vo = rowsum[tid * 4 + 3] + pxo;
                float c = sigf(vf) * c_s[tid] + sigf(vi) * tanhf_(vg);
                float h = sigf(vo) * tanhf_(c);
                c_s[tid] = c;
                g_h[l][t][jb + tid] = h;
            }
            __syncthreads();
            if (tid == 0) {
                __threadfence();                 // make h slice visible
                asm volatile("st.release.gpu.u32 [%0], %1;"
                             :: "l"(&g_flag[l][t][cid]), "r"(1u) : "memory");
            }
        }
    }
}

// ---------------------------------------------------------------- K3: mlp1
__global__ void k_mlp1(Ptrs P) {
    int row  = blockIdx.x * 8 + (threadIdx.x >> 5);
    int lane = threadIdx.x & 31;
    const float* xseg[4] = { g_h[0][LP], g_h[1][LP], g_h[2][TMAX], g_h[3][TMAX] };
    const float4* w = (const float4*)(P.w1 + row * NGATE);
    float a0 = 0.f, a1 = 0.f, a2 = 0.f, a3 = 0.f;
#pragma unroll
    for (int k = 0; k < 32; k++) {
        int c4  = k * 32 + lane;                  // float4 idx in [0,1024)
        int seg = c4 >> 8;                        // 256 float4 per 1024-seg
        float4 xv = ((const float4*)xseg[seg])[c4 & 255];
        float4 wv = w[c4];
        a0 = fmaf(wv.x, xv.x, a0);
        a1 = fmaf(wv.y, xv.y, a1);
        a2 = fmaf(wv.z, xv.z, a2);
        a3 = fmaf(wv.w, xv.w, a3);
    }
    float a = (a0 + a1) + (a2 + a3);
#pragma unroll
    for (int off = 16; off; off >>= 1) a += __shfl_xor_sync(0xffffffffu, a, off);
    if (lane == 0) g_h1[row] = fmaxf(a + P.b1[row], 0.0f);
}

// ---------------------------------------------------------------- K4: mlp2
__global__ void k_mlp2(Ptrs P, float* out) {
    __shared__ float red[32];
    int tid = threadIdx.x;                         // 1024 threads
    float a = 0.f;
    for (int k = tid; k < NGATE; k += 1024) a = fmaf(g_h1[k], P.w2[k], a);
#pragma unroll
    for (int off = 16; off; off >>= 1) a += __shfl_xor_sync(0xffffffffu, a, off);
    if ((tid & 31) == 0) red[tid >> 5] = a;
    __syncthreads();
    if (tid < 32) {
        float v = red[tid];
#pragma unroll
        for (int off = 16; off; off >>= 1) v += __shfl_xor_sync(0xffffffffu, v, off);
        if (tid == 0) out[0] = v + P.b2[0];
    }
}

// ---------------------------------------------------------------------------
extern "C" void kernel_launch(void* const* d_in, const int* in_sizes, int n_in,
                              void* d_out, int out_size) {
    Ptrs P;
    P.x_pep = (const float*)d_in[0];
    P.x_hla = (const float*)d_in[1];
    // l: 0 pep_f, 1 pep_b, 2 hla_f, 3 hla_b ; groups of (wih, whh, bih, bhh)
    for (int l = 0; l < 4; l++) {
        P.wih[l] = (const float*)d_in[2 + 4 * l + 0];
        P.whh[l] = (const float*)d_in[2 + 4 * l + 1];
        P.bih[l] = (const float*)d_in[2 + 4 * l + 2];
        P.bhh[l] = (const float*)d_in[2 + 4 * l + 3];
    }
    P.w1 = (const float*)d_in[18];
    P.b1 = (const float*)d_in[19];
    P.w2 = (const float*)d_in[20];
    P.b2 = (const float*)d_in[21];

    cudaFuncSetAttribute(k_lstm, cudaFuncAttributeMaxDynamicSharedMemorySize,
                         SMEM_BYTES);

    k_init<<<(NFLAG + 255) / 256 + 1, 256>>>();
    dim3 gxg(TMAX, 4);
    k_xg<<<gxg, 256>>>(P);
    k_lstm<<<GRID, NTHR, SMEM_BYTES>>>(P);
    k_mlp1<<<NGATE / 8, 256>>>(P);
    k_mlp2<<<1, 1024>>>(P, (float*)d_out);
}

// round 5
// speedup vs baseline: 1.5440x; 1.5440x over previous
#include <cuda_runtime.h>
#include <cuda_bf16.h>
#include <cuda_fp16.h>

// ---------------------------------------------------------------------------
// NetMHCpan BiLSTM (pep 15 steps + hla 372 steps, H=1024) + MLP(4096->4096->1)
//
//  K2 lstm: persistent 148-CTA kernel; 74 CTAs per direction; each CTA owns
//           13-14 hidden indices -> 52-56 rows of Whh resident in SMEM as
//           FP16 (converted at load; fp32 h + fp32 accumulate).
//           Sync per step: producers red.relaxed.gpu.add on one of 8 counter
//           words (cid&7) -> RMW tail ~270cyc instead of 2000; consumer
//           warp0 acquire-polls the 8 words (one 32B sector = one L2
//           request/iteration) and sums with __reduce_add_sync.
//           Release path: warp0 STG h slice, __syncwarp, tid0 __threadfence
//           + red (classic observed-writes + fence idiom, one bar fewer).
// ---------------------------------------------------------------------------

#define TMAX   372
#define LP     15
#define H      1024
#define NGATE  4096
#define NCTA_L 74          // CTAs per LSTM direction
#define GRID   148
#define NTHR   256

#define MAXIDX 14          // max hidden indices per CTA
#define MAXROW (MAXIDX*4)  // 56
#define SMEM_BYTES (MAXROW*1024*2)   // 114688 B: fp16 weight rows

#define NCW    8           // counter words per (l,t)
#define NCNT   (4 * (TMAX + 1) * NCW)

struct Ptrs {
    const float* x_pep;
    const float* x_hla;
    const float* wih[4];
    const float* whh[4];
    const float* bih[4];
    const float* bhh[4];
    const float* w1;
    const float* b1;
    const float* w2;
    const float* b2;
};

// l: 0=pep_f 1=pep_b 2=hla_f 3=hla_b
__device__ float    g_h[4][TMAX + 1][H];        // hidden states per step
__device__ float    g_xg[4][TMAX][NGATE];       // input projections + biases
__device__ unsigned g_cnt[4][TMAX + 1][NCW];    // split step counters
__device__ float    g_h1[NGATE];                // MLP hidden

__device__ __forceinline__ float sigf(float x) {
    return 1.0f / (1.0f + __expf(-x));
}
__device__ __forceinline__ float tanhf_(float x) {
    float e = __expf(2.0f * x);
    return 1.0f - 2.0f / (e + 1.0f);
}

// ---------------------------------------------------------------- K0: init
__global__ void k_init() {
    int tid = blockIdx.x * blockDim.x + threadIdx.x;
    if (tid < NCNT) {
        // cnt[l][0][*] = 10 (step 0 ready: 8*10*4lanes >= 296), others 0
        int rem = tid % ((TMAX + 1) * NCW);
        ((unsigned*)g_cnt)[tid] = (rem < NCW) ? 10u : 0u;
    }
    if (tid < 4 * H) {
        int l = tid >> 10;
        g_h[l][0][tid & (H - 1)] = 0.0f;
    }
}

// ---------------------------------------------------------------- K1: xg
__global__ void k_xg(Ptrs P) {
    int t = blockIdx.x;
    int l = blockIdx.y;
    int T = (l < 2) ? LP : TMAX;
    if (t >= T) return;
    const float* x = (l < 2) ? P.x_pep : P.x_hla;
    int te = (l & 1) ? (T - 1 - t) : t;      // backward dir: reversed input

    __shared__ float xs[21];
    if (threadIdx.x < 21) xs[threadIdx.x] = x[te * 21 + threadIdx.x];
    __syncthreads();

    const float* wih = P.wih[l];
    const float* ba  = P.bih[l];
    const float* bb  = P.bhh[l];
    for (int r = threadIdx.x; r < NGATE; r += blockDim.x) {
        float a = ba[r] + bb[r];
        const float* w = wih + r * 21;
#pragma unroll
        for (int i = 0; i < 21; i++) a = fmaf(xs[i], w[i], a);
        g_xg[l][t][r] = a;
    }
}

// ---------------------------------------------------------------- K2: lstm
__global__ void __launch_bounds__(NTHR, 1) k_lstm(Ptrs P) {
    extern __shared__ __half w_s[];          // [nrows][1024] fp16
    __shared__ float rowsum[MAXROW];
    __shared__ float c_s[MAXIDX];

    const int tid  = threadIdx.x;
    const int lane = tid & 31;
    const int warp = tid >> 5;
    const int cta  = blockIdx.x;
    const int dir  = (cta >= NCTA_L) ? 1 : 0;
    const int cid  = cta - dir * NCTA_L;
    const int jb   = (cid * H) / NCTA_L;
    const int je   = ((cid + 1) * H) / NCTA_L;
    const int nidx = je - jb;                // 13 or 14
    const int nrows = nidx * 4;

    for (int phase = 0; phase < 2; phase++) {
        const int l = phase * 2 + dir;
        const int T = phase ? TMAX : LP;
        const float4* whh4 = (const float4*)P.whh[l];

        __syncthreads();   // protect w_s / c_s reuse across phases
        // load + convert this CTA's weight rows to fp16 SMEM
        for (int idx = tid; idx < nrows * 256; idx += NTHR) {
            int r  = idx >> 8;
            int c4 = idx & 255;
            int li = r >> 2, g = r & 3;
            int grow = g * H + jb + li;      // global row in [4096,1024]
            float4 w = whh4[grow * 256 + c4];
            __half2* dst = (__half2*)w_s + r * 512 + c4 * 2;
            dst[0] = __floats2half2_rn(w.x, w.y);
            dst[1] = __floats2half2_rn(w.z, w.w);
        }
        if (tid < MAXIDX) c_s[tid] = 0.0f;
        __syncthreads();

        for (int t = 1; t <= T; t++) {
            // ---- prefetch xg gate values (independent of h[t-1])
            float pxi = 0.f, pxf = 0.f, pxg = 0.f, pxo = 0.f;
            if (tid < nidx) {
                const float* xg = g_xg[l][t - 1];
                int j = jb + tid;
                pxi = xg[j];
                pxf = xg[H + j];
                pxg = xg[2 * H + j];
                pxo = xg[3 * H + j];
            }

            // ---- wait for all 74 producers: poll 8 counter words (1 sector)
            if (warp == 0) {
                const unsigned* cw = g_cnt[l][t - 1];
                int f = lane & 7;            // each word read by 4 lanes
                unsigned s;
                do {
                    unsigned v;
                    asm volatile("ld.acquire.gpu.u32 %0, [%1];"
                                 : "=r"(v) : "l"(cw + f) : "memory");
                    s = __reduce_add_sync(0xffffffffu, v);
                } while (s < 296u);          // 74 producers x 4 reads each
            }
            __syncthreads();

            // ---- load h[t-1]: lane covers cols k*256+lane*8 .. +8
            const float4* hsrc = (const float4*)g_h[l][t - 1];
            float4 hA[4], hB[4];
#pragma unroll
            for (int k = 0; k < 4; k++) {
                hA[k] = hsrc[k * 64 + lane * 2];
                hB[k] = hsrc[k * 64 + lane * 2 + 1];
            }

            // ---- dot products: warp per row, fp16 weights, fp32 accumulate
            const uint4* wsu = (const uint4*)w_s;
            for (int r = warp; r < nrows; r += (NTHR / 32)) {
                float a0 = 0.f, a1 = 0.f, a2 = 0.f, a3 = 0.f;
#pragma unroll
                for (int k = 0; k < 4; k++) {
                    uint4 w = wsu[r * 128 + k * 32 + lane];
                    float2 f;
                    f = __half22float2(*(const __half2*)&w.x);
                    a0 = fmaf(f.x, hA[k].x, a0); a1 = fmaf(f.y, hA[k].y, a1);
                    f = __half22float2(*(const __half2*)&w.y);
                    a2 = fmaf(f.x, hA[k].z, a2); a3 = fmaf(f.y, hA[k].w, a3);
                    f = __half22float2(*(const __half2*)&w.z);
                    a0 = fmaf(f.x, hB[k].x, a0); a1 = fmaf(f.y, hB[k].y, a1);
                    f = __half22float2(*(const __half2*)&w.w);
                    a2 = fmaf(f.x, hB[k].z, a2); a3 = fmaf(f.y, hB[k].w, a3);
                }
                float a = (a0 + a1) + (a2 + a3);
#pragma unroll
                for (int off = 16; off; off >>= 1)
                    a += __shfl_xor_sync(0xffffffffu, a, off);
                if (lane == 0) rowsum[r] = a;
            }
            __syncthreads();

            // ---- warp0: gate, write h slice, release via fence + split red.
            // warps 1-7 run ahead to the next spin-bar, which also protects
            // rowsum from being overwritten before warp0 read it.
            if (warp == 0) {
                if (lane < nidx) {
                    float vi = rowsum[lane * 4 + 0] + pxi;
                    float vf = rowsum[lane * 4 + 1] + pxf;
                    float vg = rowsum[lane * 4 + 2] + pxg;
                    float vo = rowsum[lane * 4 + 3] + pxo;
                    float c = sigf(vf) * c_s[lane] + sigf(vi) * tanhf_(vg);
                    float h = sigf(vo) * tanhf_(c);
                    c_s[lane] = c;
                    g_h[l][t][jb + lane] = h;
                }
                __syncwarp();
                if (lane == 0) {
                    __threadfence();         // make observed h slice visible
                    asm volatile("red.relaxed.gpu.global.add.u32 [%0], %1;"
                                 :: "l"(&g_cnt[l][t][cid & 7]), "r"(1u)
                                 : "memory");
                }
            }
        }
    }
}

// ---------------------------------------------------------------- K3: mlp1
__global__ void k_mlp1(Ptrs P) {
    int row  = blockIdx.x * 8 + (threadIdx.x >> 5);
    int lane = threadIdx.x & 31;
    const float* xseg[4] = { g_h[0][LP], g_h[1][LP], g_h[2][TMAX], g_h[3][TMAX] };
    const float4* w = (const float4*)(P.w1 + row * NGATE);
    float a0 = 0.f, a1 = 0.f, a2 = 0.f, a3 = 0.f;
#pragma unroll
    for (int k = 0; k < 32; k++) {
        int c4  = k * 32 + lane;                  // float4 idx in [0,1024)
        int seg = c4 >> 8;                        // 256 float4 per 1024-seg
        float4 xv = ((const float4*)xseg[seg])[c4 & 255];
        float4 wv = w[c4];
        a0 = fmaf(wv.x, xv.x, a0);
        a1 = fmaf(wv.y, xv.y, a1);
        a2 = fmaf(wv.z, xv.z, a2);
        a3 = fmaf(wv.w, xv.w, a3);
    }
    float a = (a0 + a1) + (a2 + a3);
#pragma unroll
    for (int off = 16; off; off >>= 1) a += __shfl_xor_sync(0xffffffffu, a, off);
    if (lane == 0) g_h1[row] = fmaxf(a + P.b1[row], 0.0f);
}

// ---------------------------------------------------------------- K4: mlp2
__global__ void k_mlp2(Ptrs P, float* out) {
    __shared__ float red[32];
    int tid = threadIdx.x;                         // 1024 threads
    float a = 0.f;
    for (int k = tid; k < NGATE; k += 1024) a = fmaf(g_h1[k], P.w2[k], a);
#pragma unroll
    for (int off = 16; off; off >>= 1) a += __shfl_xor_sync(0xffffffffu, a, off);
    if ((tid & 31) == 0) red[tid >> 5] = a;
    __syncthreads();
    if (tid < 32) {
        float v = red[tid];
#pragma unroll
        for (int off = 16; off; off >>= 1) v += __shfl_xor_sync(0xffffffffu, v, off);
        if (tid == 0) out[0] = v + P.b2[0];
    }
}

// ---------------------------------------------------------------------------
extern "C" void kernel_launch(void* const* d_in, const int* in_sizes, int n_in,
                              void* d_out, int out_size) {
    Ptrs P;
    P.x_pep = (const float*)d_in[0];
    P.x_hla = (const float*)d_in[1];
    // l: 0 pep_f, 1 pep_b, 2 hla_f, 3 hla_b ; groups of (wih, whh, bih, bhh)
    for (int l = 0; l < 4; l++) {
        P.wih[l] = (const float*)d_in[2 + 4 * l + 0];
        P.whh[l] = (const float*)d_in[2 + 4 * l + 1];
        P.bih[l] = (const float*)d_in[2 + 4 * l + 2];
        P.bhh[l] = (const float*)d_in[2 + 4 * l + 3];
    }
    P.w1 = (const float*)d_in[18];
    P.b1 = (const float*)d_in[19];
    P.w2 = (const float*)d_in[20];
    P.b2 = (const float*)d_in[21];

    cudaFuncSetAttribute(k_lstm, cudaFuncAttributeMaxDynamicSharedMemorySize,
                         SMEM_BYTES);

    k_init<<<48, 256>>>();
    dim3 gxg(TMAX, 4);
    k_xg<<<gxg, 256>>>(P);
    k_lstm<<<GRID, NTHR, SMEM_BYTES>>>(P);
    k_mlp1<<<NGATE / 8, 256>>>(P);
    k_mlp2<<<1, 1024>>>(P, (float*)d_out);
}